// round 11
// baseline (speedup 1.0000x reference)
#include <cuda_runtime.h>

// ---------------------------------------------------------------------------
// GCN_13898514169996: 2-layer GCN, N=100000, E=3.2M, 512->16->7.
// gcn(h)[v] = dinv[v] * ( sum_{u->v} h[u]*dinv[u] + h[v]*dinv[v] ) + b
// dinv = rsqrt(cnt[v]+1). edge_index int32.
// Round 11: k_count keeps per-dst ordinals -> k_place is atomic-free.
// CSR build (scan+place) overlaps GEMM1 on a side stream.
// ---------------------------------------------------------------------------

#define MAXN 100000
#define MAXE 3200000

__device__ float g_hs  [MAXN * 16];  // (X@W1) * dinv[row]
__device__ float g_hs2 [MAXN * 8];   // (h1@W2) * dinv[row], padded to 8
__device__ int   g_cnt [MAXN];       // in-degree (excl. self loop)
__device__ int   g_off [MAXN];       // CSR offsets
__device__ int   g_ord [MAXE];       // per-edge ordinal within its dst bucket
__device__ int   g_eadj[MAXE];       // CSR adjacency: src ids grouped by dst
__device__ unsigned long long g_scanpack[512];  // lookback state

// ---- zero counts + scan flags ----------------------------------------------------
__global__ void k_zero(int n) {
    int v = blockIdx.x * blockDim.x + threadIdx.x;
    if (v < n) g_cnt[v] = 0;
    if (v < 512) g_scanpack[v] = 0ull;
}

// ---- in-degree count, 4 edges/thread; keep the returned ordinal -------------------
__global__ void k_count(const int* __restrict__ dst, int E) {
    int i = blockIdx.x * blockDim.x + threadIdx.x;
    int e0 = i * 4;
    if (e0 + 3 < E) {
        int4 d = __ldg((const int4*)dst + i);
        int4 o;
        o.x = atomicAdd(&g_cnt[d.x], 1);
        o.y = atomicAdd(&g_cnt[d.y], 1);
        o.z = atomicAdd(&g_cnt[d.z], 1);
        o.w = atomicAdd(&g_cnt[d.w], 1);
        *((int4*)g_ord + i) = o;
    } else {
        for (int e = e0; e < E; e++)
            g_ord[e] = atomicAdd(&g_cnt[dst[e]], 1);
    }
}

// ---- single-pass exclusive scan (decoupled lookback) -------------------------------
__global__ void __launch_bounds__(256) k_scan(int n) {
    __shared__ int warp_tot[8];
    __shared__ int s_excl;
    int t = threadIdx.x, b = blockIdx.x;
    int v = b * 256 + t;
    int val = (v < n) ? g_cnt[v] : 0;

    int lane = t & 31, w = t >> 5;
    int x = val;
    #pragma unroll
    for (int d = 1; d < 32; d <<= 1) {
        int y = __shfl_up_sync(0xffffffffu, x, d);
        if (lane >= d) x += y;
    }
    if (lane == 31) warp_tot[w] = x;
    __syncthreads();
    if (w == 0) {
        int wt = (lane < 8) ? warp_tot[lane] : 0;
        #pragma unroll
        for (int d = 1; d < 8; d <<= 1) {
            int y = __shfl_up_sync(0xffffffffu, wt, d);
            if (lane >= d) wt += y;
        }
        if (lane < 8) warp_tot[lane] = wt;
    }
    __syncthreads();

    int local_excl  = x - val + ((w > 0) ? warp_tot[w - 1] : 0);
    int block_total = warp_tot[7];

    if (t == 0) {
        atomicExch(&g_scanpack[b], ((unsigned long long)block_total << 2) | 1ull);
        long long run = 0;
        int j = b - 1;
        while (j >= 0) {
            unsigned long long pk;
            do { pk = atomicAdd(&g_scanpack[j], 0ull); } while ((pk & 3ull) == 0ull);
            run += (long long)(pk >> 2);
            if ((pk & 3ull) == 2ull) break;
            j--;
        }
        s_excl = (int)run;
        atomicExch(&g_scanpack[b],
                   ((unsigned long long)(run + block_total) << 2) | 2ull);
    }
    __syncthreads();

    if (v < n) g_off[v] = s_excl + local_excl;
}

// ---- CSR placement, atomic-free: slot = off[dst] + ord -----------------------------
__global__ void k_place(const int* __restrict__ src,
                        const int* __restrict__ dst, int E) {
    int i = blockIdx.x * blockDim.x + threadIdx.x;
    int e0 = i * 4;
    if (e0 + 3 < E) {
        int4 d = __ldg((const int4*)dst + i);
        int4 s = __ldg((const int4*)src + i);
        int4 o = *((const int4*)g_ord + i);
        g_eadj[g_off[d.x] + o.x] = s.x;
        g_eadj[g_off[d.y] + o.y] = s.y;
        g_eadj[g_off[d.z] + o.z] = s.z;
        g_eadj[g_off[d.w] + o.w] = s.w;
    } else {
        for (int e = e0; e < E; e++)
            g_eadj[g_off[dst[e]] + g_ord[e]] = src[e];
    }
}

// ---- GEMM1: hs = (X @ W1) * dinv[row] -----------------------------------------------
__global__ void __launch_bounds__(128, 7) k_gemm1(const float* __restrict__ x,
                                                  const float* __restrict__ W1,
                                                  int n) {
    __shared__ float Xs[128 * 36];   // [row][k_local] stride 36 (pad 4)
    __shared__ float Wsc[32 * 16];   // [k_local][col]

    int t    = threadIdx.x;
    int c    = t & 3;
    int rg   = t >> 2;
    int row0 = blockIdx.x * 128;

    float acc[4][4];
    #pragma unroll
    for (int i = 0; i < 4; i++)
        #pragma unroll
        for (int j = 0; j < 4; j++) acc[i][j] = 0.f;

    int sq  = t & 7;
    int sr  = t >> 3;
    int wkl = t >> 2;
    int wjj = (t & 3) * 4;

    #pragma unroll 1
    for (int ch = 0; ch < 16; ch++) {
        int k0 = ch * 32;
        __syncthreads();
        *(float4*)(Wsc + wkl * 16 + wjj) =
            *(const float4*)(W1 + (size_t)(k0 + wkl) * 16 + wjj);
        #pragma unroll
        for (int p = 0; p < 8; p++) {
            int rl = p * 16 + sr;
            int gr = row0 + rl; if (gr > n - 1) gr = n - 1;
            float4 v = __ldg((const float4*)(x + (size_t)gr * 512 + k0) + sq);
            *(float4*)(Xs + rl * 36 + sq * 4) = v;
        }
        __syncthreads();

        #pragma unroll
        for (int k4 = 0; k4 < 8; k4++) {
            float4 w0 = *(float4*)(Wsc + (k4 * 4 + 0) * 16 + c * 4);
            float4 w1 = *(float4*)(Wsc + (k4 * 4 + 1) * 16 + c * 4);
            float4 w2 = *(float4*)(Wsc + (k4 * 4 + 2) * 16 + c * 4);
            float4 w3 = *(float4*)(Wsc + (k4 * 4 + 3) * 16 + c * 4);
            #pragma unroll
            for (int i = 0; i < 4; i++) {
                float4 xv = *(float4*)(Xs + (rg + 32 * i) * 36 + k4 * 4);
                acc[i][0] += xv.x * w0.x + xv.y * w1.x + xv.z * w2.x + xv.w * w3.x;
                acc[i][1] += xv.x * w0.y + xv.y * w1.y + xv.z * w2.y + xv.w * w3.y;
                acc[i][2] += xv.x * w0.z + xv.y * w1.z + xv.z * w2.z + xv.w * w3.z;
                acc[i][3] += xv.x * w0.w + xv.y * w1.w + xv.z * w2.w + xv.w * w3.w;
            }
        }
    }

    #pragma unroll
    for (int i = 0; i < 4; i++) {
        int row = row0 + rg + 32 * i;
        if (row >= n) continue;
        float dv = rsqrtf((float)g_cnt[row] + 1.f);
        float4 o = make_float4(acc[i][0] * dv, acc[i][1] * dv,
                               acc[i][2] * dv, acc[i][3] * dv);
        *(float4*)(g_hs + (size_t)row * 16 + c * 4) = o;
    }
}

// ---- fused gather1 + layer-1 epilogue + layer-2 GEMM ---------------------------------
__global__ void __launch_bounds__(256) k_gl1(const float* __restrict__ b1,
                                             const float* __restrict__ W2,
                                             int n) {
    __shared__ float W2s[112];
    __shared__ float b1s[16];
    int t = threadIdx.x;
    if (t < 112) W2s[t] = W2[t];
    if (t < 16)  b1s[t] = b1[t];
    __syncthreads();

    int gi = blockIdx.x * 256 + t;
    int v  = gi >> 2;
    if (v >= n) return;
    int q   = gi & 3;
    int off = g_off[v];
    int cnt = g_cnt[v];

    float4 acc = make_float4(0.f, 0.f, 0.f, 0.f);
    int i = 0;
    for (; i + 2 <= cnt; i += 2) {
        int s0 = g_eadj[off + i];
        int s1 = g_eadj[off + i + 1];
        float4 a = __ldg((const float4*)(g_hs + (size_t)s0 * 16) + q);
        float4 b = __ldg((const float4*)(g_hs + (size_t)s1 * 16) + q);
        acc.x += a.x + b.x; acc.y += a.y + b.y;
        acc.z += a.z + b.z; acc.w += a.w + b.w;
    }
    if (i < cnt) {
        int s0 = g_eadj[off + i];
        float4 a = __ldg((const float4*)(g_hs + (size_t)s0 * 16) + q);
        acc.x += a.x; acc.y += a.y; acc.z += a.z; acc.w += a.w;
    }

    float dv = rsqrtf((float)cnt + 1.f);
    float4 self = *(const float4*)(g_hs + (size_t)v * 16 + q * 4);
    float h0 = fmaxf(fmaf(dv, acc.x + self.x, b1s[q * 4 + 0]), 0.f);
    float h1 = fmaxf(fmaf(dv, acc.y + self.y, b1s[q * 4 + 1]), 0.f);
    float h2 = fmaxf(fmaf(dv, acc.z + self.z, b1s[q * 4 + 2]), 0.f);
    float h3 = fmaxf(fmaf(dv, acc.w + self.w, b1s[q * 4 + 3]), 0.f);

    float o[7];
    #pragma unroll
    for (int j = 0; j < 7; j++) {
        const float* wq = W2s + (q * 4) * 7 + j;
        o[j] = h0 * wq[0] + h1 * wq[7] + h2 * wq[14] + h3 * wq[21];
    }
    #pragma unroll
    for (int j = 0; j < 7; j++) {
        o[j] += __shfl_xor_sync(0xffffffffu, o[j], 1);
        o[j] += __shfl_xor_sync(0xffffffffu, o[j], 2);
    }

    if (q == 0)
        *(float4*)(g_hs2 + (size_t)v * 8) =
            make_float4(o[0] * dv, o[1] * dv, o[2] * dv, o[3] * dv);
    else if (q == 1)
        *(float4*)(g_hs2 + (size_t)v * 8 + 4) =
            make_float4(o[4] * dv, o[5] * dv, o[6] * dv, 0.f);
}

// ---- fused gather2 + final (bias + log_softmax) ---------------------------------------
__global__ void __launch_bounds__(256) k_gl2(const float* __restrict__ b2,
                                             float* __restrict__ out, int n) {
    int gi = blockIdx.x * 256 + threadIdx.x;
    int v  = gi >> 1;
    if (v >= n) return;
    int q   = gi & 1;
    int off = g_off[v];
    int cnt = g_cnt[v];

    float4 acc = make_float4(0.f, 0.f, 0.f, 0.f);
    int i = 0;
    for (; i + 2 <= cnt; i += 2) {
        int s0 = g_eadj[off + i];
        int s1 = g_eadj[off + i + 1];
        float4 a = __ldg((const float4*)(g_hs2 + (size_t)s0 * 8) + q);
        float4 b = __ldg((const float4*)(g_hs2 + (size_t)s1 * 8) + q);
        acc.x += a.x + b.x; acc.y += a.y + b.y;
        acc.z += a.z + b.z; acc.w += a.w + b.w;
    }
    if (i < cnt) {
        int s0 = g_eadj[off + i];
        float4 a = __ldg((const float4*)(g_hs2 + (size_t)s0 * 8) + q);
        acc.x += a.x; acc.y += a.y; acc.z += a.z; acc.w += a.w;
    }

    float dv = rsqrtf((float)cnt + 1.f);
    float4 self = *(const float4*)(g_hs2 + (size_t)v * 8 + q * 4);
    float m0 = fmaf(dv, acc.x + self.x, __ldg(b2 + q * 4 + 0));
    float m1 = fmaf(dv, acc.y + self.y, __ldg(b2 + q * 4 + 1));
    float m2 = fmaf(dv, acc.z + self.z, __ldg(b2 + q * 4 + 2));
    float m3 = (q == 0) ? fmaf(dv, acc.w + self.w, __ldg(b2 + 3)) : -1e30f;

    float p0 = __shfl_xor_sync(0xffffffffu, m0, 1);
    float p1 = __shfl_xor_sync(0xffffffffu, m1, 1);
    float p2 = __shfl_xor_sync(0xffffffffu, m2, 1);
    float p3 = __shfl_xor_sync(0xffffffffu, m3, 1);

    float mx = fmaxf(fmaxf(fmaxf(m0, m1), fmaxf(m2, m3)),
                     fmaxf(fmaxf(p0, p1), fmaxf(p2, p3)));
    float s = expf(m0 - mx) + expf(m1 - mx) + expf(m2 - mx) +
              expf(p0 - mx) + expf(p1 - mx) + expf(p2 - mx);
    s += (q == 0) ? expf(m3 - mx) : expf(p3 - mx);
    float l = logf(s) + mx;

    float* ov = out + (size_t)v * 7 + q * 4;
    ov[0] = m0 - l;
    ov[1] = m1 - l;
    ov[2] = m2 - l;
    if (q == 0) ov[3] = m3 - l;
}

// ---------------------------------------------------------------------------
extern "C" void kernel_launch(void* const* d_in, const int* in_sizes, int n_in,
                              void* d_out, int out_size) {
    const float* x  = (const float*)d_in[0];
    const int*   ei = (const int*)d_in[1];      // int32 (JAX x64 disabled)
    const float* W1 = (const float*)d_in[2];
    const float* b1 = (const float*)d_in[3];
    const float* W2 = (const float*)d_in[4];
    const float* b2 = (const float*)d_in[5];

    int n = in_sizes[0] / 512;     // 100000
    int E = in_sizes[1] / 2;       // 3200000
    const int* src = ei;
    const int* dst = ei + E;

    // one-time host resources (no device memory); captured work identical per call
    static cudaStream_t s2 = 0;
    static cudaEvent_t evFork = 0, evJoin = 0;
    if (!s2) {
        cudaStreamCreateWithFlags(&s2, cudaStreamNonBlocking);
        cudaEventCreateWithFlags(&evFork, cudaEventDisableTiming);
        cudaEventCreateWithFlags(&evJoin, cudaEventDisableTiming);
    }

    int nb  = (n + 255) / 256;
    int e4  = (E + 3) / 4;
    int eb4 = (e4 + 255) / 256;

    k_zero <<<nb, 256>>>(n);
    k_count<<<eb4, 256>>>(dst, E);
    cudaEventRecord(evFork, 0);

    // side stream: scan + atomic-free place — overlaps with GEMM1
    cudaStreamWaitEvent(s2, evFork, 0);
    k_scan <<<nb, 256, 0, s2>>>(n);
    k_place<<<eb4, 256, 0, s2>>>(src, dst, E);
    cudaEventRecord(evJoin, s2);

    // main stream: GEMM1 (fma-bound), independent of CSR adjacency
    k_gemm1<<<(n + 127) / 128, 128>>>(x, W1, n);
    cudaStreamWaitEvent(0, evJoin, 0);

    k_gl1  <<<(4 * n + 255) / 256, 256>>>(b1, W2, n);
    k_gl2  <<<(2 * n + 255) / 256, 256>>>(b2, (float*)d_out, n);
}

// round 12
// speedup vs baseline: 1.0095x; 1.0095x over previous
#include <cuda_runtime.h>

// ---------------------------------------------------------------------------
// GCN_13898514169996: 2-layer GCN, N=100000, E=3.2M, 512->16->7.
// gcn(h)[v] = dinv[v] * ( sum_{u->v} h[u]*dinv[u] + h[v]*dinv[v] ) + b
// dinv = rsqrt(cnt[v]+1). edge_index int32.
// Round 12: gemm1 unscaled + k_scale at join -> whole CSR build (zero,count,
// scan,place) runs on a side stream fully parallel to gemm1.
// ---------------------------------------------------------------------------

#define MAXN 100000
#define MAXE 3200000

__device__ float g_hs  [MAXN * 16];  // X@W1 (unscaled until k_scale)
__device__ float g_hs2 [MAXN * 8];   // (h1@W2) * dinv[row], padded to 8
__device__ int   g_cnt [MAXN];       // in-degree (excl. self loop)
__device__ int   g_off [MAXN];       // CSR offsets
__device__ int   g_ord [MAXE];       // per-edge ordinal within its dst bucket
__device__ int   g_eadj[MAXE];       // CSR adjacency: src ids grouped by dst
__device__ unsigned long long g_scanpack[512];  // lookback state

// ---- zero counts + scan flags ----------------------------------------------------
__global__ void k_zero(int n) {
    int v = blockIdx.x * blockDim.x + threadIdx.x;
    if (v < n) g_cnt[v] = 0;
    if (v < 512) g_scanpack[v] = 0ull;
}

// ---- in-degree count, 4 edges/thread; keep the returned ordinal -------------------
__global__ void k_count(const int* __restrict__ dst, int E) {
    int i = blockIdx.x * blockDim.x + threadIdx.x;
    int e0 = i * 4;
    if (e0 + 3 < E) {
        int4 d = __ldg((const int4*)dst + i);
        int4 o;
        o.x = atomicAdd(&g_cnt[d.x], 1);
        o.y = atomicAdd(&g_cnt[d.y], 1);
        o.z = atomicAdd(&g_cnt[d.z], 1);
        o.w = atomicAdd(&g_cnt[d.w], 1);
        *((int4*)g_ord + i) = o;
    } else {
        for (int e = e0; e < E; e++)
            g_ord[e] = atomicAdd(&g_cnt[dst[e]], 1);
    }
}

// ---- single-pass exclusive scan (decoupled lookback) -------------------------------
__global__ void __launch_bounds__(256) k_scan(int n) {
    __shared__ int warp_tot[8];
    __shared__ int s_excl;
    int t = threadIdx.x, b = blockIdx.x;
    int v = b * 256 + t;
    int val = (v < n) ? g_cnt[v] : 0;

    int lane = t & 31, w = t >> 5;
    int x = val;
    #pragma unroll
    for (int d = 1; d < 32; d <<= 1) {
        int y = __shfl_up_sync(0xffffffffu, x, d);
        if (lane >= d) x += y;
    }
    if (lane == 31) warp_tot[w] = x;
    __syncthreads();
    if (w == 0) {
        int wt = (lane < 8) ? warp_tot[lane] : 0;
        #pragma unroll
        for (int d = 1; d < 8; d <<= 1) {
            int y = __shfl_up_sync(0xffffffffu, wt, d);
            if (lane >= d) wt += y;
        }
        if (lane < 8) warp_tot[lane] = wt;
    }
    __syncthreads();

    int local_excl  = x - val + ((w > 0) ? warp_tot[w - 1] : 0);
    int block_total = warp_tot[7];

    if (t == 0) {
        atomicExch(&g_scanpack[b], ((unsigned long long)block_total << 2) | 1ull);
        long long run = 0;
        int j = b - 1;
        while (j >= 0) {
            unsigned long long pk;
            do { pk = atomicAdd(&g_scanpack[j], 0ull); } while ((pk & 3ull) == 0ull);
            run += (long long)(pk >> 2);
            if ((pk & 3ull) == 2ull) break;
            j--;
        }
        s_excl = (int)run;
        atomicExch(&g_scanpack[b],
                   ((unsigned long long)(run + block_total) << 2) | 2ull);
    }
    __syncthreads();

    if (v < n) g_off[v] = s_excl + local_excl;
}

// ---- CSR placement, atomic-free: slot = off[dst] + ord -----------------------------
__global__ void k_place(const int* __restrict__ src,
                        const int* __restrict__ dst, int E) {
    int i = blockIdx.x * blockDim.x + threadIdx.x;
    int e0 = i * 4;
    if (e0 + 3 < E) {
        int4 d = __ldg((const int4*)dst + i);
        int4 s = __ldg((const int4*)src + i);
        int4 o = *((const int4*)g_ord + i);
        g_eadj[g_off[d.x] + o.x] = s.x;
        g_eadj[g_off[d.y] + o.y] = s.y;
        g_eadj[g_off[d.z] + o.z] = s.z;
        g_eadj[g_off[d.w] + o.w] = s.w;
    } else {
        for (int e = e0; e < E; e++)
            g_eadj[g_off[dst[e]] + g_ord[e]] = src[e];
    }
}

// ---- GEMM1 (unscaled): hs = X @ W1 -------------------------------------------------
__global__ void __launch_bounds__(128, 7) k_gemm1(const float* __restrict__ x,
                                                  const float* __restrict__ W1,
                                                  int n) {
    __shared__ float Xs[128 * 36];   // [row][k_local] stride 36 (pad 4)
    __shared__ float Wsc[32 * 16];   // [k_local][col]

    int t    = threadIdx.x;
    int c    = t & 3;
    int rg   = t >> 2;
    int row0 = blockIdx.x * 128;

    float acc[4][4];
    #pragma unroll
    for (int i = 0; i < 4; i++)
        #pragma unroll
        for (int j = 0; j < 4; j++) acc[i][j] = 0.f;

    int sq  = t & 7;
    int sr  = t >> 3;
    int wkl = t >> 2;
    int wjj = (t & 3) * 4;

    #pragma unroll 1
    for (int ch = 0; ch < 16; ch++) {
        int k0 = ch * 32;
        __syncthreads();
        *(float4*)(Wsc + wkl * 16 + wjj) =
            *(const float4*)(W1 + (size_t)(k0 + wkl) * 16 + wjj);
        #pragma unroll
        for (int p = 0; p < 8; p++) {
            int rl = p * 16 + sr;
            int gr = row0 + rl; if (gr > n - 1) gr = n - 1;
            float4 v = __ldg((const float4*)(x + (size_t)gr * 512 + k0) + sq);
            *(float4*)(Xs + rl * 36 + sq * 4) = v;
        }
        __syncthreads();

        #pragma unroll
        for (int k4 = 0; k4 < 8; k4++) {
            float4 w0 = *(float4*)(Wsc + (k4 * 4 + 0) * 16 + c * 4);
            float4 w1 = *(float4*)(Wsc + (k4 * 4 + 1) * 16 + c * 4);
            float4 w2 = *(float4*)(Wsc + (k4 * 4 + 2) * 16 + c * 4);
            float4 w3 = *(float4*)(Wsc + (k4 * 4 + 3) * 16 + c * 4);
            #pragma unroll
            for (int i = 0; i < 4; i++) {
                float4 xv = *(float4*)(Xs + (rg + 32 * i) * 36 + k4 * 4);
                acc[i][0] += xv.x * w0.x + xv.y * w1.x + xv.z * w2.x + xv.w * w3.x;
                acc[i][1] += xv.x * w0.y + xv.y * w1.y + xv.z * w2.y + xv.w * w3.y;
                acc[i][2] += xv.x * w0.z + xv.y * w1.z + xv.z * w2.z + xv.w * w3.z;
                acc[i][3] += xv.x * w0.w + xv.y * w1.w + xv.z * w2.w + xv.w * w3.w;
            }
        }
    }

    #pragma unroll
    for (int i = 0; i < 4; i++) {
        int row = row0 + rg + 32 * i;
        if (row >= n) continue;
        *(float4*)(g_hs + (size_t)row * 16 + c * 4) =
            make_float4(acc[i][0], acc[i][1], acc[i][2], acc[i][3]);
    }
}

// ---- scale hs rows by dinv (after count joins) -------------------------------------
__global__ void k_scale(int n) {
    int gi = blockIdx.x * blockDim.x + threadIdx.x;
    int v  = gi >> 2;
    if (v >= n) return;
    float dv = rsqrtf((float)g_cnt[v] + 1.f);
    float4* p = (float4*)(g_hs + (size_t)v * 16) + (gi & 3);
    float4 a = *p;
    *p = make_float4(a.x * dv, a.y * dv, a.z * dv, a.w * dv);
}

// ---- fused gather1 + layer-1 epilogue + layer-2 GEMM ---------------------------------
__global__ void __launch_bounds__(256) k_gl1(const float* __restrict__ b1,
                                             const float* __restrict__ W2,
                                             int n) {
    __shared__ float W2s[112];
    __shared__ float b1s[16];
    int t = threadIdx.x;
    if (t < 112) W2s[t] = W2[t];
    if (t < 16)  b1s[t] = b1[t];
    __syncthreads();

    int gi = blockIdx.x * 256 + t;
    int v  = gi >> 2;
    if (v >= n) return;
    int q   = gi & 3;
    int off = g_off[v];
    int cnt = g_cnt[v];

    float4 acc = make_float4(0.f, 0.f, 0.f, 0.f);
    int i = 0;
    for (; i + 2 <= cnt; i += 2) {
        int s0 = g_eadj[off + i];
        int s1 = g_eadj[off + i + 1];
        float4 a = __ldg((const float4*)(g_hs + (size_t)s0 * 16) + q);
        float4 b = __ldg((const float4*)(g_hs + (size_t)s1 * 16) + q);
        acc.x += a.x + b.x; acc.y += a.y + b.y;
        acc.z += a.z + b.z; acc.w += a.w + b.w;
    }
    if (i < cnt) {
        int s0 = g_eadj[off + i];
        float4 a = __ldg((const float4*)(g_hs + (size_t)s0 * 16) + q);
        acc.x += a.x; acc.y += a.y; acc.z += a.z; acc.w += a.w;
    }

    float dv = rsqrtf((float)cnt + 1.f);
    float4 self = *(const float4*)(g_hs + (size_t)v * 16 + q * 4);
    float h0 = fmaxf(fmaf(dv, acc.x + self.x, b1s[q * 4 + 0]), 0.f);
    float h1 = fmaxf(fmaf(dv, acc.y + self.y, b1s[q * 4 + 1]), 0.f);
    float h2 = fmaxf(fmaf(dv, acc.z + self.z, b1s[q * 4 + 2]), 0.f);
    float h3 = fmaxf(fmaf(dv, acc.w + self.w, b1s[q * 4 + 3]), 0.f);

    float o[7];
    #pragma unroll
    for (int j = 0; j < 7; j++) {
        const float* wq = W2s + (q * 4) * 7 + j;
        o[j] = h0 * wq[0] + h1 * wq[7] + h2 * wq[14] + h3 * wq[21];
    }
    #pragma unroll
    for (int j = 0; j < 7; j++) {
        o[j] += __shfl_xor_sync(0xffffffffu, o[j], 1);
        o[j] += __shfl_xor_sync(0xffffffffu, o[j], 2);
    }

    if (q == 0)
        *(float4*)(g_hs2 + (size_t)v * 8) =
            make_float4(o[0] * dv, o[1] * dv, o[2] * dv, o[3] * dv);
    else if (q == 1)
        *(float4*)(g_hs2 + (size_t)v * 8 + 4) =
            make_float4(o[4] * dv, o[5] * dv, o[6] * dv, 0.f);
}

// ---- fused gather2 + final (bias + log_softmax) ---------------------------------------
__global__ void __launch_bounds__(256) k_gl2(const float* __restrict__ b2,
                                             float* __restrict__ out, int n) {
    int gi = blockIdx.x * 256 + threadIdx.x;
    int v  = gi >> 1;
    if (v >= n) return;
    int q   = gi & 1;
    int off = g_off[v];
    int cnt = g_cnt[v];

    float4 acc = make_float4(0.f, 0.f, 0.f, 0.f);
    int i = 0;
    for (; i + 2 <= cnt; i += 2) {
        int s0 = g_eadj[off + i];
        int s1 = g_eadj[off + i + 1];
        float4 a = __ldg((const float4*)(g_hs2 + (size_t)s0 * 8) + q);
        float4 b = __ldg((const float4*)(g_hs2 + (size_t)s1 * 8) + q);
        acc.x += a.x + b.x; acc.y += a.y + b.y;
        acc.z += a.z + b.z; acc.w += a.w + b.w;
    }
    if (i < cnt) {
        int s0 = g_eadj[off + i];
        float4 a = __ldg((const float4*)(g_hs2 + (size_t)s0 * 8) + q);
        acc.x += a.x; acc.y += a.y; acc.z += a.z; acc.w += a.w;
    }

    float dv = rsqrtf((float)cnt + 1.f);
    float4 self = *(const float4*)(g_hs2 + (size_t)v * 8 + q * 4);
    float m0 = fmaf(dv, acc.x + self.x, __ldg(b2 + q * 4 + 0));
    float m1 = fmaf(dv, acc.y + self.y, __ldg(b2 + q * 4 + 1));
    float m2 = fmaf(dv, acc.z + self.z, __ldg(b2 + q * 4 + 2));
    float m3 = (q == 0) ? fmaf(dv, acc.w + self.w, __ldg(b2 + 3)) : -1e30f;

    float p0 = __shfl_xor_sync(0xffffffffu, m0, 1);
    float p1 = __shfl_xor_sync(0xffffffffu, m1, 1);
    float p2 = __shfl_xor_sync(0xffffffffu, m2, 1);
    float p3 = __shfl_xor_sync(0xffffffffu, m3, 1);

    float mx = fmaxf(fmaxf(fmaxf(m0, m1), fmaxf(m2, m3)),
                     fmaxf(fmaxf(p0, p1), fmaxf(p2, p3)));
    float s = expf(m0 - mx) + expf(m1 - mx) + expf(m2 - mx) +
              expf(p0 - mx) + expf(p1 - mx) + expf(p2 - mx);
    s += (q == 0) ? expf(m3 - mx) : expf(p3 - mx);
    float l = logf(s) + mx;

    float* ov = out + (size_t)v * 7 + q * 4;
    ov[0] = m0 - l;
    ov[1] = m1 - l;
    ov[2] = m2 - l;
    if (q == 0) ov[3] = m3 - l;
}

// ---------------------------------------------------------------------------
extern "C" void kernel_launch(void* const* d_in, const int* in_sizes, int n_in,
                              void* d_out, int out_size) {
    const float* x  = (const float*)d_in[0];
    const int*   ei = (const int*)d_in[1];      // int32 (JAX x64 disabled)
    const float* W1 = (const float*)d_in[2];
    const float* b1 = (const float*)d_in[3];
    const float* W2 = (const float*)d_in[4];
    const float* b2 = (const float*)d_in[5];

    int n = in_sizes[0] / 512;     // 100000
    int E = in_sizes[1] / 2;       // 3200000
    const int* src = ei;
    const int* dst = ei + E;

    // one-time host resources (no device memory); captured work identical per call
    static cudaStream_t s2 = 0;
    static cudaEvent_t evFork = 0, evJoin = 0;
    if (!s2) {
        cudaStreamCreateWithFlags(&s2, cudaStreamNonBlocking);
        cudaEventCreateWithFlags(&evFork, cudaEventDisableTiming);
        cudaEventCreateWithFlags(&evJoin, cudaEventDisableTiming);
    }

    int nb  = (n + 255) / 256;
    int e4  = (E + 3) / 4;
    int eb4 = (e4 + 255) / 256;

    // fork immediately: side stream does the whole CSR build,
    // main stream does the (count-independent) unscaled GEMM1.
    cudaEventRecord(evFork, 0);
    cudaStreamWaitEvent(s2, evFork, 0);

    k_zero <<<nb, 256, 0, s2>>>(n);
    k_count<<<eb4, 256, 0, s2>>>(dst, E);
    k_scan <<<nb, 256, 0, s2>>>(n);
    k_place<<<eb4, 256, 0, s2>>>(src, dst, E);
    cudaEventRecord(evJoin, s2);

    k_gemm1<<<(n + 127) / 128, 128>>>(x, W1, n);
    cudaStreamWaitEvent(0, evJoin, 0);

    k_scale<<<(4 * n + 255) / 256, 256>>>(n);
    k_gl1  <<<(4 * n + 255) / 256, 256>>>(b1, W2, n);
    k_gl2  <<<(2 * n + 255) / 256, 256>>>(b2, (float*)d_out, n);
}

// round 13
// speedup vs baseline: 1.0363x; 1.0265x over previous
#include <cuda_runtime.h>
#include <cuda_fp16.h>

// ---------------------------------------------------------------------------
// GCN_13898514169996: 2-layer GCN, N=100000, E=3.2M, 512->16->7.
// gcn(h)[v] = dinv[v] * ( sum_{u->v} h[u]*dinv[u] + h[v]*dinv[v] ) + b
// dinv = rsqrt(cnt[v]+1). edge_index int32.
// Round 13: fp16 storage for hs / hs2 (fp32 accumulation everywhere) ->
// gather traffic halves. CSR build overlaps GEMM1 on a side stream.
// ---------------------------------------------------------------------------

#define MAXN 100000
#define MAXE 3200000

__device__ float g_hsraw[MAXN * 16];  // X@W1, fp32, unscaled
__device__ uint4 g_hs  [MAXN * 2];    // (X@W1)*dinv as 16 halves/row (2x uint4)
__device__ uint4 g_hs2 [MAXN];        // (h1@W2)*dinv as 7 halves + pad
__device__ int   g_cnt [MAXN];
__device__ int   g_off [MAXN];
__device__ int   g_ord [MAXE];
__device__ int   g_eadj[MAXE];
__device__ unsigned long long g_scanpack[512];

// accumulate 8 halves (one uint4) into fp32 acc[8]
__device__ __forceinline__ void acc8(float* acc, uint4 u) {
    float2 f;
    f = __half22float2(*(__half2*)&u.x); acc[0] += f.x; acc[1] += f.y;
    f = __half22float2(*(__half2*)&u.y); acc[2] += f.x; acc[3] += f.y;
    f = __half22float2(*(__half2*)&u.z); acc[4] += f.x; acc[5] += f.y;
    f = __half22float2(*(__half2*)&u.w); acc[6] += f.x; acc[7] += f.y;
}
__device__ __forceinline__ void unpack8(float* f, uint4 u) {
    float2 t;
    t = __half22float2(*(__half2*)&u.x); f[0] = t.x; f[1] = t.y;
    t = __half22float2(*(__half2*)&u.y); f[2] = t.x; f[3] = t.y;
    t = __half22float2(*(__half2*)&u.z); f[4] = t.x; f[5] = t.y;
    t = __half22float2(*(__half2*)&u.w); f[6] = t.x; f[7] = t.y;
}

// ---- zero counts + scan flags ------------------------------------------------------
__global__ void k_zero(int n) {
    int v = blockIdx.x * blockDim.x + threadIdx.x;
    if (v < n) g_cnt[v] = 0;
    if (v < 512) g_scanpack[v] = 0ull;
}

// ---- in-degree count, 4 edges/thread; keep the returned ordinal --------------------
__global__ void k_count(const int* __restrict__ dst, int E) {
    int i = blockIdx.x * blockDim.x + threadIdx.x;
    int e0 = i * 4;
    if (e0 + 3 < E) {
        int4 d = __ldg((const int4*)dst + i);
        int4 o;
        o.x = atomicAdd(&g_cnt[d.x], 1);
        o.y = atomicAdd(&g_cnt[d.y], 1);
        o.z = atomicAdd(&g_cnt[d.z], 1);
        o.w = atomicAdd(&g_cnt[d.w], 1);
        *((int4*)g_ord + i) = o;
    } else {
        for (int e = e0; e < E; e++)
            g_ord[e] = atomicAdd(&g_cnt[dst[e]], 1);
    }
}

// ---- single-pass exclusive scan (decoupled lookback) -------------------------------
__global__ void __launch_bounds__(256) k_scan(int n) {
    __shared__ int warp_tot[8];
    __shared__ int s_excl;
    int t = threadIdx.x, b = blockIdx.x;
    int v = b * 256 + t;
    int val = (v < n) ? g_cnt[v] : 0;

    int lane = t & 31, w = t >> 5;
    int x = val;
    #pragma unroll
    for (int d = 1; d < 32; d <<= 1) {
        int y = __shfl_up_sync(0xffffffffu, x, d);
        if (lane >= d) x += y;
    }
    if (lane == 31) warp_tot[w] = x;
    __syncthreads();
    if (w == 0) {
        int wt = (lane < 8) ? warp_tot[lane] : 0;
        #pragma unroll
        for (int d = 1; d < 8; d <<= 1) {
            int y = __shfl_up_sync(0xffffffffu, wt, d);
            if (lane >= d) wt += y;
        }
        if (lane < 8) warp_tot[lane] = wt;
    }
    __syncthreads();

    int local_excl  = x - val + ((w > 0) ? warp_tot[w - 1] : 0);
    int block_total = warp_tot[7];

    if (t == 0) {
        atomicExch(&g_scanpack[b], ((unsigned long long)block_total << 2) | 1ull);
        long long run = 0;
        int j = b - 1;
        while (j >= 0) {
            unsigned long long pk;
            do { pk = atomicAdd(&g_scanpack[j], 0ull); } while ((pk & 3ull) == 0ull);
            run += (long long)(pk >> 2);
            if ((pk & 3ull) == 2ull) break;
            j--;
        }
        s_excl = (int)run;
        atomicExch(&g_scanpack[b],
                   ((unsigned long long)(run + block_total) << 2) | 2ull);
    }
    __syncthreads();

    if (v < n) g_off[v] = s_excl + local_excl;
}

// ---- CSR placement, atomic-free: slot = off[dst] + ord ------------------------------
__global__ void k_place(const int* __restrict__ src,
                        const int* __restrict__ dst, int E) {
    int i = blockIdx.x * blockDim.x + threadIdx.x;
    int e0 = i * 4;
    if (e0 + 3 < E) {
        int4 d = __ldg((const int4*)dst + i);
        int4 s = __ldg((const int4*)src + i);
        int4 o = *((const int4*)g_ord + i);
        g_eadj[g_off[d.x] + o.x] = s.x;
        g_eadj[g_off[d.y] + o.y] = s.y;
        g_eadj[g_off[d.z] + o.z] = s.z;
        g_eadj[g_off[d.w] + o.w] = s.w;
    } else {
        for (int e = e0; e < E; e++)
            g_eadj[g_off[dst[e]] + g_ord[e]] = src[e];
    }
}

// ---- GEMM1 (unscaled): hsraw = X @ W1 ----------------------------------------------
__global__ void __launch_bounds__(128, 7) k_gemm1(const float* __restrict__ x,
                                                  const float* __restrict__ W1,
                                                  int n) {
    __shared__ float Xs[128 * 36];
    __shared__ float Wsc[32 * 16];

    int t    = threadIdx.x;
    int c    = t & 3;
    int rg   = t >> 2;
    int row0 = blockIdx.x * 128;

    float acc[4][4];
    #pragma unroll
    for (int i = 0; i < 4; i++)
        #pragma unroll
        for (int j = 0; j < 4; j++) acc[i][j] = 0.f;

    int sq  = t & 7;
    int sr  = t >> 3;
    int wkl = t >> 2;
    int wjj = (t & 3) * 4;

    #pragma unroll 1
    for (int ch = 0; ch < 16; ch++) {
        int k0 = ch * 32;
        __syncthreads();
        *(float4*)(Wsc + wkl * 16 + wjj) =
            *(const float4*)(W1 + (size_t)(k0 + wkl) * 16 + wjj);
        #pragma unroll
        for (int p = 0; p < 8; p++) {
            int rl = p * 16 + sr;
            int gr = row0 + rl; if (gr > n - 1) gr = n - 1;
            float4 v = __ldg((const float4*)(x + (size_t)gr * 512 + k0) + sq);
            *(float4*)(Xs + rl * 36 + sq * 4) = v;
        }
        __syncthreads();

        #pragma unroll
        for (int k4 = 0; k4 < 8; k4++) {
            float4 w0 = *(float4*)(Wsc + (k4 * 4 + 0) * 16 + c * 4);
            float4 w1 = *(float4*)(Wsc + (k4 * 4 + 1) * 16 + c * 4);
            float4 w2 = *(float4*)(Wsc + (k4 * 4 + 2) * 16 + c * 4);
            float4 w3 = *(float4*)(Wsc + (k4 * 4 + 3) * 16 + c * 4);
            #pragma unroll
            for (int i = 0; i < 4; i++) {
                float4 xv = *(float4*)(Xs + (rg + 32 * i) * 36 + k4 * 4);
                acc[i][0] += xv.x * w0.x + xv.y * w1.x + xv.z * w2.x + xv.w * w3.x;
                acc[i][1] += xv.x * w0.y + xv.y * w1.y + xv.z * w2.y + xv.w * w3.y;
                acc[i][2] += xv.x * w0.z + xv.y * w1.z + xv.z * w2.z + xv.w * w3.z;
                acc[i][3] += xv.x * w0.w + xv.y * w1.w + xv.z * w2.w + xv.w * w3.w;
            }
        }
    }

    #pragma unroll
    for (int i = 0; i < 4; i++) {
        int row = row0 + rg + 32 * i;
        if (row >= n) continue;
        *(float4*)(g_hsraw + (size_t)row * 16 + c * 4) =
            make_float4(acc[i][0], acc[i][1], acc[i][2], acc[i][3]);
    }
}

// ---- scale by dinv and quantize to fp16 (4 threads/node) ---------------------------
__global__ void k_scale(int n) {
    int gi = blockIdx.x * blockDim.x + threadIdx.x;
    int v  = gi >> 2;
    if (v >= n) return;
    int q = gi & 3;
    float dv = rsqrtf((float)g_cnt[v] + 1.f);
    float4 a = *((const float4*)(g_hsraw + (size_t)v * 16) + q);
    __half2 h0 = __float22half2_rn(make_float2(a.x * dv, a.y * dv));
    __half2 h1 = __float22half2_rn(make_float2(a.z * dv, a.w * dv));
    uint2 u;
    u.x = *(unsigned*)&h0;
    u.y = *(unsigned*)&h1;
    ((uint2*)g_hs)[(size_t)v * 4 + q] = u;
}

// ---- fused gather1 + layer-1 epilogue + layer-2 GEMM (2 threads/node) ---------------
__global__ void __launch_bounds__(256) k_gl1(const float* __restrict__ b1,
                                             const float* __restrict__ W2,
                                             int n) {
    __shared__ float W2s[112];
    __shared__ float b1s[16];
    int t = threadIdx.x;
    if (t < 112) W2s[t] = W2[t];
    if (t < 16)  b1s[t] = b1[t];
    __syncthreads();

    int gi = blockIdx.x * 256 + t;
    int v  = gi >> 1;
    if (v >= n) return;
    int q   = gi & 1;                 // features q*8 .. q*8+7
    int off = g_off[v];
    int cnt = g_cnt[v];

    float acc[8];
    #pragma unroll
    for (int j = 0; j < 8; j++) acc[j] = 0.f;

    int i = 0;
    for (; i + 4 <= cnt; i += 4) {
        int s0 = g_eadj[off + i + 0];
        int s1 = g_eadj[off + i + 1];
        int s2 = g_eadj[off + i + 2];
        int s3 = g_eadj[off + i + 3];
        uint4 u0 = g_hs[(size_t)s0 * 2 + q];
        uint4 u1 = g_hs[(size_t)s1 * 2 + q];
        uint4 u2 = g_hs[(size_t)s2 * 2 + q];
        uint4 u3 = g_hs[(size_t)s3 * 2 + q];
        acc8(acc, u0); acc8(acc, u1); acc8(acc, u2); acc8(acc, u3);
    }
    for (; i < cnt; i++) {
        int s0 = g_eadj[off + i];
        acc8(acc, g_hs[(size_t)s0 * 2 + q]);
    }

    float dv = rsqrtf((float)cnt + 1.f);
    float self[8];
    unpack8(self, g_hs[(size_t)v * 2 + q]);

    float h[8];
    #pragma unroll
    for (int j = 0; j < 8; j++)
        h[j] = fmaxf(fmaf(dv, acc[j] + self[j], b1s[q * 8 + j]), 0.f);

    float o[7];
    #pragma unroll
    for (int j = 0; j < 7; j++) {
        const float* wq = W2s + (q * 8) * 7 + j;
        float s = h[0] * wq[0];
        s += h[1] * wq[7];
        s += h[2] * wq[14];
        s += h[3] * wq[21];
        s += h[4] * wq[28];
        s += h[5] * wq[35];
        s += h[6] * wq[42];
        s += h[7] * wq[49];
        o[j] = s;
    }
    #pragma unroll
    for (int j = 0; j < 7; j++)
        o[j] += __shfl_xor_sync(0xffffffffu, o[j], 1);

    if (q == 0) {
        __half2 p0 = __float22half2_rn(make_float2(o[0] * dv, o[1] * dv));
        __half2 p1 = __float22half2_rn(make_float2(o[2] * dv, o[3] * dv));
        __half2 p2 = __float22half2_rn(make_float2(o[4] * dv, o[5] * dv));
        __half2 p3 = __float22half2_rn(make_float2(o[6] * dv, 0.f));
        uint4 u;
        u.x = *(unsigned*)&p0; u.y = *(unsigned*)&p1;
        u.z = *(unsigned*)&p2; u.w = *(unsigned*)&p3;
        g_hs2[v] = u;
    }
}

// ---- fused gather2 + final (1 thread/node) ------------------------------------------
__global__ void __launch_bounds__(256) k_gl2(const float* __restrict__ b2,
                                             float* __restrict__ out, int n) {
    int v = blockIdx.x * 256 + threadIdx.x;
    if (v >= n) return;
    int off = g_off[v];
    int cnt = g_cnt[v];

    float acc[8];
    #pragma unroll
    for (int j = 0; j < 8; j++) acc[j] = 0.f;

    int i = 0;
    for (; i + 4 <= cnt; i += 4) {
        int s0 = g_eadj[off + i + 0];
        int s1 = g_eadj[off + i + 1];
        int s2 = g_eadj[off + i + 2];
        int s3 = g_eadj[off + i + 3];
        uint4 u0 = g_hs2[s0];
        uint4 u1 = g_hs2[s1];
        uint4 u2 = g_hs2[s2];
        uint4 u3 = g_hs2[s3];
        acc8(acc, u0); acc8(acc, u1); acc8(acc, u2); acc8(acc, u3);
    }
    for (; i < cnt; i++) acc8(acc, g_hs2[g_eadj[off + i]]);

    float dv = rsqrtf((float)cnt + 1.f);
    float self[8];
    unpack8(self, g_hs2[v]);

    float m[7];
    #pragma unroll
    for (int j = 0; j < 7; j++)
        m[j] = fmaf(dv, acc[j] + self[j], __ldg(b2 + j));

    float mx = m[0];
    #pragma unroll
    for (int j = 1; j < 7; j++) mx = fmaxf(mx, m[j]);
    float s = 0.f;
    #pragma unroll
    for (int j = 0; j < 7; j++) s += expf(m[j] - mx);
    float l = logf(s) + mx;

    float* ov = out + (size_t)v * 7;
    #pragma unroll
    for (int j = 0; j < 7; j++) ov[j] = m[j] - l;
}

// ---------------------------------------------------------------------------
extern "C" void kernel_launch(void* const* d_in, const int* in_sizes, int n_in,
                              void* d_out, int out_size) {
    const float* x  = (const float*)d_in[0];
    const int*   ei = (const int*)d_in[1];      // int32 (JAX x64 disabled)
    const float* W1 = (const float*)d_in[2];
    const float* b1 = (const float*)d_in[3];
    const float* W2 = (const float*)d_in[4];
    const float* b2 = (const float*)d_in[5];

    int n = in_sizes[0] / 512;     // 100000
    int E = in_sizes[1] / 2;       // 3200000
    const int* src = ei;
    const int* dst = ei + E;

    static cudaStream_t s2 = 0;
    static cudaEvent_t evFork = 0, evJoin = 0;
    if (!s2) {
        cudaStreamCreateWithFlags(&s2, cudaStreamNonBlocking);
        cudaEventCreateWithFlags(&evFork, cudaEventDisableTiming);
        cudaEventCreateWithFlags(&evJoin, cudaEventDisableTiming);
    }

    int nb  = (n + 255) / 256;
    int e4  = (E + 3) / 4;
    int eb4 = (e4 + 255) / 256;

    cudaEventRecord(evFork, 0);
    cudaStreamWaitEvent(s2, evFork, 0);

    k_zero <<<nb, 256, 0, s2>>>(n);
    k_count<<<eb4, 256, 0, s2>>>(dst, E);
    k_scan <<<nb, 256, 0, s2>>>(n);
    k_place<<<eb4, 256, 0, s2>>>(src, dst, E);
    cudaEventRecord(evJoin, s2);

    k_gemm1<<<(n + 127) / 128, 128>>>(x, W1, n);
    cudaStreamWaitEvent(0, evJoin, 0);

    k_scale<<<(4 * n + 255) / 256, 256>>>(n);
    k_gl1  <<<(2 * n + 255) / 256, 256>>>(b1, W2, n);
    k_gl2  <<<(n + 255) / 256, 256>>>(b2, (float*)d_out, n);
}

// round 14
// speedup vs baseline: 1.2041x; 1.1620x over previous
#include <cuda_runtime.h>
#include <cuda_fp16.h>
#include <mma.h>

using namespace nvcuda;

// ---------------------------------------------------------------------------
// GCN_13898514169996: 2-layer GCN, N=100000, E=3.2M, 512->16->7.
// gcn(h)[v] = dinv[v] * ( sum_{u->v} h[u]*dinv[u] + h[v]*dinv[v] ) + b
// dinv = rsqrt(cnt[v]+1). edge_index int32.
// Round 14: GEMM1 on tensor cores (fp16 wmma, fp32 accum). fp16 hs/hs2
// gather tables. CSR build overlaps GEMM1 on a side stream.
// ---------------------------------------------------------------------------

#define MAXN  100000
#define MAXNP 100096   // padded rows for wmma tail stores
#define MAXE  3200000

__device__ float g_hsraw[MAXNP * 16]; // X@W1, fp32, unscaled (padded)
__device__ uint4 g_hs  [MAXN * 2];    // (X@W1)*dinv as 16 halves/row
__device__ uint4 g_hs2 [MAXN];        // (h1@W2)*dinv as 7 halves + pad
__device__ int   g_cnt [MAXN];
__device__ int   g_off [MAXN];
__device__ int   g_ord [MAXE];
__device__ int   g_eadj[MAXE];
__device__ unsigned long long g_scanpack[512];

__device__ __forceinline__ void acc8(float* acc, uint4 u) {
    float2 f;
    f = __half22float2(*(__half2*)&u.x); acc[0] += f.x; acc[1] += f.y;
    f = __half22float2(*(__half2*)&u.y); acc[2] += f.x; acc[3] += f.y;
    f = __half22float2(*(__half2*)&u.z); acc[4] += f.x; acc[5] += f.y;
    f = __half22float2(*(__half2*)&u.w); acc[6] += f.x; acc[7] += f.y;
}
__device__ __forceinline__ void unpack8(float* f, uint4 u) {
    float2 t;
    t = __half22float2(*(__half2*)&u.x); f[0] = t.x; f[1] = t.y;
    t = __half22float2(*(__half2*)&u.y); f[2] = t.x; f[3] = t.y;
    t = __half22float2(*(__half2*)&u.z); f[4] = t.x; f[5] = t.y;
    t = __half22float2(*(__half2*)&u.w); f[6] = t.x; f[7] = t.y;
}

// ---- zero counts + scan flags ------------------------------------------------------
__global__ void k_zero(int n) {
    int v = blockIdx.x * blockDim.x + threadIdx.x;
    if (v < n) g_cnt[v] = 0;
    if (v < 512) g_scanpack[v] = 0ull;
}

// ---- in-degree count, 4 edges/thread; keep the returned ordinal --------------------
__global__ void k_count(const int* __restrict__ dst, int E) {
    int i = blockIdx.x * blockDim.x + threadIdx.x;
    int e0 = i * 4;
    if (e0 + 3 < E) {
        int4 d = __ldg((const int4*)dst + i);
        int4 o;
        o.x = atomicAdd(&g_cnt[d.x], 1);
        o.y = atomicAdd(&g_cnt[d.y], 1);
        o.z = atomicAdd(&g_cnt[d.z], 1);
        o.w = atomicAdd(&g_cnt[d.w], 1);
        *((int4*)g_ord + i) = o;
    } else {
        for (int e = e0; e < E; e++)
            g_ord[e] = atomicAdd(&g_cnt[dst[e]], 1);
    }
}

// ---- single-pass exclusive scan (decoupled lookback) -------------------------------
__global__ void __launch_bounds__(256) k_scan(int n) {
    __shared__ int warp_tot[8];
    __shared__ int s_excl;
    int t = threadIdx.x, b = blockIdx.x;
    int v = b * 256 + t;
    int val = (v < n) ? g_cnt[v] : 0;

    int lane = t & 31, w = t >> 5;
    int x = val;
    #pragma unroll
    for (int d = 1; d < 32; d <<= 1) {
        int y = __shfl_up_sync(0xffffffffu, x, d);
        if (lane >= d) x += y;
    }
    if (lane == 31) warp_tot[w] = x;
    __syncthreads();
    if (w == 0) {
        int wt = (lane < 8) ? warp_tot[lane] : 0;
        #pragma unroll
        for (int d = 1; d < 8; d <<= 1) {
            int y = __shfl_up_sync(0xffffffffu, wt, d);
            if (lane >= d) wt += y;
        }
        if (lane < 8) warp_tot[lane] = wt;
    }
    __syncthreads();

    int local_excl  = x - val + ((w > 0) ? warp_tot[w - 1] : 0);
    int block_total = warp_tot[7];

    if (t == 0) {
        atomicExch(&g_scanpack[b], ((unsigned long long)block_total << 2) | 1ull);
        long long run = 0;
        int j = b - 1;
        while (j >= 0) {
            unsigned long long pk;
            do { pk = atomicAdd(&g_scanpack[j], 0ull); } while ((pk & 3ull) == 0ull);
            run += (long long)(pk >> 2);
            if ((pk & 3ull) == 2ull) break;
            j--;
        }
        s_excl = (int)run;
        atomicExch(&g_scanpack[b],
                   ((unsigned long long)(run + block_total) << 2) | 2ull);
    }
    __syncthreads();

    if (v < n) g_off[v] = s_excl + local_excl;
}

// ---- CSR placement, atomic-free: slot = off[dst] + ord ------------------------------
__global__ void k_place(const int* __restrict__ src,
                        const int* __restrict__ dst, int E) {
    int i = blockIdx.x * blockDim.x + threadIdx.x;
    int e0 = i * 4;
    if (e0 + 3 < E) {
        int4 d = __ldg((const int4*)dst + i);
        int4 s = __ldg((const int4*)src + i);
        int4 o = *((const int4*)g_ord + i);
        g_eadj[g_off[d.x] + o.x] = s.x;
        g_eadj[g_off[d.y] + o.y] = s.y;
        g_eadj[g_off[d.z] + o.z] = s.z;
        g_eadj[g_off[d.w] + o.w] = s.w;
    } else {
        for (int e = e0; e < E; e++)
            g_eadj[g_off[dst[e]] + g_ord[e]] = src[e];
    }
}

// ---- GEMM1 on tensor cores: hsraw = X @ W1 (fp16 in, fp32 accum) --------------------
// 128 threads = 4 warps; 64 rows/block (16 per warp); K chunked at 64.
__global__ void __launch_bounds__(128) k_gemm1(const float* __restrict__ x,
                                               const float* __restrict__ W1,
                                               int n) {
    __shared__ __half Xh[64][72];   // 64 rows x 64 k halves, pad 8 (16B)
    __shared__ __half Wh[64][16];   // k x j chunk

    int t    = threadIdx.x;
    int warp = t >> 5;
    int row0 = blockIdx.x * 64;

    wmma::fragment<wmma::accumulator, 16, 16, 16, float> cfrag;
    wmma::fill_fragment(cfrag, 0.f);

    #pragma unroll 1
    for (int ch = 0; ch < 8; ch++) {
        int k0 = ch * 64;
        __syncthreads();
        // stage W chunk: 64x16 halves
        #pragma unroll
        for (int u = 0; u < 8; u++) {
            int idx = t + u * 128;
            int kk = idx >> 4, jj = idx & 15;
            Wh[kk][jj] = __float2half(W1[(size_t)(k0 + kk) * 16 + jj]);
        }
        // stage X chunk: 64 rows x 64 k, fp32 -> half (coalesced float4 loads)
        #pragma unroll
        for (int u = 0; u < 8; u++) {
            int idx = t + u * 128;
            int rl = idx >> 4;
            int kq = (idx & 15) * 4;
            int gr = row0 + rl; if (gr > n - 1) gr = n - 1;
            float4 v = __ldg((const float4*)(x + (size_t)gr * 512 + k0 + kq));
            Xh[rl][kq + 0] = __float2half(v.x);
            Xh[rl][kq + 1] = __float2half(v.y);
            Xh[rl][kq + 2] = __float2half(v.z);
            Xh[rl][kq + 3] = __float2half(v.w);
        }
        __syncthreads();

        #pragma unroll
        for (int ks = 0; ks < 4; ks++) {
            wmma::fragment<wmma::matrix_a, 16, 16, 16, __half, wmma::row_major> afrag;
            wmma::fragment<wmma::matrix_b, 16, 16, 16, __half, wmma::row_major> bfrag;
            wmma::load_matrix_sync(afrag, &Xh[warp * 16][ks * 16], 72);
            wmma::load_matrix_sync(bfrag, &Wh[ks * 16][0], 16);
            wmma::mma_sync(cfrag, afrag, bfrag, cfrag);
        }
    }

    // store 16x16 fp32 tile (padded g_hsraw absorbs tail rows)
    wmma::store_matrix_sync(g_hsraw + (size_t)(row0 + warp * 16) * 16,
                            cfrag, 16, wmma::mem_row_major);
}

// ---- scale by dinv and quantize to fp16 (4 threads/node) ---------------------------
__global__ void k_scale(int n) {
    int gi = blockIdx.x * blockDim.x + threadIdx.x;
    int v  = gi >> 2;
    if (v >= n) return;
    int q = gi & 3;
    float dv = rsqrtf((float)g_cnt[v] + 1.f);
    float4 a = *((const float4*)(g_hsraw + (size_t)v * 16) + q);
    __half2 h0 = __float22half2_rn(make_float2(a.x * dv, a.y * dv));
    __half2 h1 = __float22half2_rn(make_float2(a.z * dv, a.w * dv));
    uint2 u;
    u.x = *(unsigned*)&h0;
    u.y = *(unsigned*)&h1;
    ((uint2*)g_hs)[(size_t)v * 4 + q] = u;
}

// ---- fused gather1 + layer-1 epilogue + layer-2 GEMM (2 threads/node) ---------------
__global__ void __launch_bounds__(256) k_gl1(const float* __restrict__ b1,
                                             const float* __restrict__ W2,
                                             int n) {
    __shared__ float W2s[112];
    __shared__ float b1s[16];
    int t = threadIdx.x;
    if (t < 112) W2s[t] = W2[t];
    if (t < 16)  b1s[t] = b1[t];
    __syncthreads();

    int gi = blockIdx.x * 256 + t;
    int v  = gi >> 1;
    if (v >= n) return;
    int q   = gi & 1;                 // features q*8 .. q*8+7
    int off = g_off[v];
    int cnt = g_cnt[v];

    float acc[8];
    #pragma unroll
    for (int j = 0; j < 8; j++) acc[j] = 0.f;

    int i = 0;
    for (; i + 4 <= cnt; i += 4) {
        int s0 = g_eadj[off + i + 0];
        int s1 = g_eadj[off + i + 1];
        int s2 = g_eadj[off + i + 2];
        int s3 = g_eadj[off + i + 3];
        uint4 u0 = g_hs[(size_t)s0 * 2 + q];
        uint4 u1 = g_hs[(size_t)s1 * 2 + q];
        uint4 u2 = g_hs[(size_t)s2 * 2 + q];
        uint4 u3 = g_hs[(size_t)s3 * 2 + q];
        acc8(acc, u0); acc8(acc, u1); acc8(acc, u2); acc8(acc, u3);
    }
    for (; i < cnt; i++) {
        int s0 = g_eadj[off + i];
        acc8(acc, g_hs[(size_t)s0 * 2 + q]);
    }

    float dv = rsqrtf((float)cnt + 1.f);
    float self[8];
    unpack8(self, g_hs[(size_t)v * 2 + q]);

    float h[8];
    #pragma unroll
    for (int j = 0; j < 8; j++)
        h[j] = fmaxf(fmaf(dv, acc[j] + self[j], b1s[q * 8 + j]), 0.f);

    float o[7];
    #pragma unroll
    for (int j = 0; j < 7; j++) {
        const float* wq = W2s + (q * 8) * 7 + j;
        float s = h[0] * wq[0];
        s += h[1] * wq[7];
        s += h[2] * wq[14];
        s += h[3] * wq[21];
        s += h[4] * wq[28];
        s += h[5] * wq[35];
        s += h[6] * wq[42];
        s += h[7] * wq[49];
        o[j] = s;
    }
    #pragma unroll
    for (int j = 0; j < 7; j++)
        o[j] += __shfl_xor_sync(0xffffffffu, o[j], 1);

    if (q == 0) {
        __half2 p0 = __float22half2_rn(make_float2(o[0] * dv, o[1] * dv));
        __half2 p1 = __float22half2_rn(make_float2(o[2] * dv, o[3] * dv));
        __half2 p2 = __float22half2_rn(make_float2(o[4] * dv, o[5] * dv));
        __half2 p3 = __float22half2_rn(make_float2(o[6] * dv, 0.f));
        uint4 u;
        u.x = *(unsigned*)&p0; u.y = *(unsigned*)&p1;
        u.z = *(unsigned*)&p2; u.w = *(unsigned*)&p3;
        g_hs2[v] = u;
    }
}

// ---- fused gather2 + final (1 thread/node) ------------------------------------------
__global__ void __launch_bounds__(256) k_gl2(const float* __restrict__ b2,
                                             float* __restrict__ out, int n) {
    int v = blockIdx.x * 256 + threadIdx.x;
    if (v >= n) return;
    int off = g_off[v];
    int cnt = g_cnt[v];

    float acc[8];
    #pragma unroll
    for (int j = 0; j < 8; j++) acc[j] = 0.f;

    int i = 0;
    for (; i + 4 <= cnt; i += 4) {
        int s0 = g_eadj[off + i + 0];
        int s1 = g_eadj[off + i + 1];
        int s2 = g_eadj[off + i + 2];
        int s3 = g_eadj[off + i + 3];
        uint4 u0 = g_hs2[s0];
        uint4 u1 = g_hs2[s1];
        uint4 u2 = g_hs2[s2];
        uint4 u3 = g_hs2[s3];
        acc8(acc, u0); acc8(acc, u1); acc8(acc, u2); acc8(acc, u3);
    }
    for (; i < cnt; i++) acc8(acc, g_hs2[g_eadj[off + i]]);

    float dv = rsqrtf((float)cnt + 1.f);
    float self[8];
    unpack8(self, g_hs2[v]);

    float m[7];
    #pragma unroll
    for (int j = 0; j < 7; j++)
        m[j] = fmaf(dv, acc[j] + self[j], __ldg(b2 + j));

    float mx = m[0];
    #pragma unroll
    for (int j = 1; j < 7; j++) mx = fmaxf(mx, m[j]);
    float s = 0.f;
    #pragma unroll
    for (int j = 0; j < 7; j++) s += expf(m[j] - mx);
    float l = logf(s) + mx;

    float* ov = out + (size_t)v * 7;
    #pragma unroll
    for (int j = 0; j < 7; j++) ov[j] = m[j] - l;
}

// ---------------------------------------------------------------------------
extern "C" void kernel_launch(void* const* d_in, const int* in_sizes, int n_in,
                              void* d_out, int out_size) {
    const float* x  = (const float*)d_in[0];
    const int*   ei = (const int*)d_in[1];      // int32 (JAX x64 disabled)
    const float* W1 = (const float*)d_in[2];
    const float* b1 = (const float*)d_in[3];
    const float* W2 = (const float*)d_in[4];
    const float* b2 = (const float*)d_in[5];

    int n = in_sizes[0] / 512;     // 100000
    int E = in_sizes[1] / 2;       // 3200000
    const int* src = ei;
    const int* dst = ei + E;

    static cudaStream_t s2 = 0;
    static cudaEvent_t evFork = 0, evJoin = 0;
    if (!s2) {
        cudaStreamCreateWithFlags(&s2, cudaStreamNonBlocking);
        cudaEventCreateWithFlags(&evFork, cudaEventDisableTiming);
        cudaEventCreateWithFlags(&evJoin, cudaEventDisableTiming);
    }

    int nb  = (n + 255) / 256;
    int e4  = (E + 3) / 4;
    int eb4 = (e4 + 255) / 256;

    cudaEventRecord(evFork, 0);
    cudaStreamWaitEvent(s2, evFork, 0);

    k_zero <<<nb, 256, 0, s2>>>(n);
    k_count<<<eb4, 256, 0, s2>>>(dst, E);
    k_scan <<<nb, 256, 0, s2>>>(n);
    k_place<<<eb4, 256, 0, s2>>>(src, dst, E);
    cudaEventRecord(evJoin, s2);

    k_gemm1<<<(n + 63) / 64, 128>>>(x, W1, n);
    cudaStreamWaitEvent(0, evJoin, 0);

    k_scale<<<(4 * n + 255) / 256, 256>>>(n);
    k_gl1  <<<(2 * n + 255) / 256, 256>>>(b1, W2, n);
    k_gl2  <<<(n + 255) / 256, 256>>>(b2, (float*)d_out, n);
}